// round 1
// baseline (speedup 1.0000x reference)
#include <cuda_runtime.h>
#include <math.h>
#include <float.h>

#define BB   4
#define NN   4096
#define DD   1024
#define WW   128
#define NWIN (NN / WW)          // 32
#define MTOT (BB * NN)          // 16384

// Scratch: q, k projections and attention output. (v is dead code in the
// reference: v2 = k2, so we never compute the v columns of the QKV GEMM.)
__device__ float g_q [(size_t)BB * NN * DD];
__device__ float g_k [(size_t)BB * NN * DD];
__device__ float g_ao[(size_t)BB * NN * DD];

// ---------------------------------------------------------------------------
// GEMM: C[M, Ncols] = A[M, 1024] @ B[1024, ldb] (+ bias)
// MODE 0: A = x, B = w_qkv (ldb=3072), Ncols=2048, split-write into g_q / g_k
// MODE 1: A = g_ao, B = w_out (ldb=1024), Ncols=1024, + bias, write d_out
// 128x128 block tile, 8x8 per-thread microtile, 256 threads, K-tile = 8.
// ---------------------------------------------------------------------------
template <int MODE>
__global__ __launch_bounds__(256) void gemm_kernel(
    const float* __restrict__ A_in,
    const float* __restrict__ Bw,
    const float* __restrict__ bias,
    float* __restrict__ Out)
{
    constexpr int K   = 1024;
    constexpr int LDB = (MODE == 0) ? 3072 : 1024;

    __shared__ float As[8][132];
    __shared__ float Bs[8][132];

    const float* __restrict__ A = (MODE == 0) ? A_in : (const float*)g_ao;

    const int t  = threadIdx.x;
    const int m0 = blockIdx.y * 128;
    const int n0 = blockIdx.x * 128;
    const int ty = t >> 4;          // 0..15
    const int tx = t & 15;          // 0..15

    // A-tile load map: each thread loads one float4 (4 consecutive k)
    const int lm  = t >> 1;         // 0..127 (row within tile)
    const int lkq = (t & 1) * 4;    // 0 or 4
    // B-tile load map: each thread loads one float4 (4 consecutive n)
    const int lkk = t >> 5;         // 0..7
    const int ln4 = (t & 31) * 4;   // 0..124

    float acc[8][8] = {};

    for (int kt = 0; kt < K; kt += 8) {
        float4 a4 = *(const float4*)&A[(size_t)(m0 + lm) * K + kt + lkq];
        As[lkq + 0][lm] = a4.x;
        As[lkq + 1][lm] = a4.y;
        As[lkq + 2][lm] = a4.z;
        As[lkq + 3][lm] = a4.w;

        float4 b4 = *(const float4*)&Bw[(size_t)(kt + lkk) * LDB + n0 + ln4];
        Bs[lkk][ln4 + 0] = b4.x;
        Bs[lkk][ln4 + 1] = b4.y;
        Bs[lkk][ln4 + 2] = b4.z;
        Bs[lkk][ln4 + 3] = b4.w;

        __syncthreads();

        #pragma unroll
        for (int kk = 0; kk < 8; kk++) {
            float rA[8], rB[8];
            #pragma unroll
            for (int i = 0; i < 8; i++) rA[i] = As[kk][ty * 8 + i];
            #pragma unroll
            for (int j = 0; j < 8; j++) rB[j] = Bs[kk][tx * 8 + j];
            #pragma unroll
            for (int i = 0; i < 8; i++)
                #pragma unroll
                for (int j = 0; j < 8; j++)
                    acc[i][j] = fmaf(rA[i], rB[j], acc[i][j]);
        }
        __syncthreads();
    }

    #pragma unroll
    for (int i = 0; i < 8; i++) {
        const int gm = m0 + ty * 8 + i;
        #pragma unroll
        for (int j = 0; j < 8; j++) {
            const int gn = n0 + tx * 8 + j;
            float v = acc[i][j];
            if (MODE == 0) {
                if (gn < 1024) g_q[(size_t)gm * 1024 + gn]          = v;
                else           g_k[(size_t)gm * 1024 + (gn - 1024)] = v;
            } else {
                Out[(size_t)gm * 1024 + gn] = v + bias[gn];
            }
        }
    }
}

// ---------------------------------------------------------------------------
// Local attention, one block per (window, batch).
//   sim[128,256] = q_win @ [k_{w-1}; k_w]^T * scale   (k_{-1} == 0, NOT masked)
//   causal mask: key j valid iff j <= i + 128
//   softmax rows, then out[128,1024] = attn @ k2   (values == keys, ref bug)
// sim lives in dynamic smem; both matmul phases use 8x8 microtiles.
// ---------------------------------------------------------------------------
#define SIMLD 260
#define TLD   132
#define ATTN_SMEM_BYTES ((128 * SIMLD + 2 * 8 * TLD) * (int)sizeof(float))

__global__ __launch_bounds__(256) void attn_kernel()
{
    extern __shared__ float sh[];
    float* sim = sh;                        // [128][SIMLD]
    float* As  = sh + 128 * SIMLD;          // [8][TLD]
    float* Bs  = As + 8 * TLD;              // [8][TLD]

    const int t  = threadIdx.x;
    const int w  = blockIdx.x;              // window 0..31
    const int b  = blockIdx.y;              // batch 0..3
    const int ty = t >> 4;
    const int tx = t & 15;
    const float scale = 0.03125f;           // DIM_INNER^-0.5 = 1/32

    const size_t qbase = ((size_t)b * NN + (size_t)w * WW) * DD;

    const int lm  = t >> 1;
    const int lkq = (t & 1) * 4;

    // ---- Phase A: sim = q @ k2^T (two 128-key halves) ----
    for (int nblk = 0; nblk < 2; nblk++) {
        float acc[8][8] = {};
        const int  tokbase = (w - 1 + nblk) * WW;   // token of key row n: tokbase+n
        const bool valid   = (tokbase >= 0);        // w==0, nblk==0 -> zero block

        for (int kt = 0; kt < DD; kt += 8) {
            float4 a4 = *(const float4*)&g_q[qbase + (size_t)lm * DD + kt + lkq];
            As[(lkq + 0) * TLD + lm] = a4.x;
            As[(lkq + 1) * TLD + lm] = a4.y;
            As[(lkq + 2) * TLD + lm] = a4.z;
            As[(lkq + 3) * TLD + lm] = a4.w;

            float4 b4 = make_float4(0.f, 0.f, 0.f, 0.f);
            if (valid)
                b4 = *(const float4*)&g_k[((size_t)b * NN + tokbase + lm) * DD + kt + lkq];
            Bs[(lkq + 0) * TLD + lm] = b4.x;
            Bs[(lkq + 1) * TLD + lm] = b4.y;
            Bs[(lkq + 2) * TLD + lm] = b4.z;
            Bs[(lkq + 3) * TLD + lm] = b4.w;

            __syncthreads();
            #pragma unroll
            for (int kk = 0; kk < 8; kk++) {
                float rA[8], rB[8];
                #pragma unroll
                for (int i = 0; i < 8; i++) rA[i] = As[kk * TLD + ty * 8 + i];
                #pragma unroll
                for (int j = 0; j < 8; j++) rB[j] = Bs[kk * TLD + tx * 8 + j];
                #pragma unroll
                for (int i = 0; i < 8; i++)
                    #pragma unroll
                    for (int j = 0; j < 8; j++)
                        acc[i][j] = fmaf(rA[i], rB[j], acc[i][j]);
            }
            __syncthreads();
        }
        #pragma unroll
        for (int i = 0; i < 8; i++)
            #pragma unroll
            for (int j = 0; j < 8; j++)
                sim[(ty * 8 + i) * SIMLD + nblk * 128 + tx * 8 + j] = acc[i][j] * scale;
    }
    __syncthreads();

    // ---- Softmax over 256 keys per row, mask j > i + 128 ----
    {
        const int warp = t >> 5;
        const int lane = t & 31;
        for (int r = warp; r < 128; r += 8) {
            const int lim = r + 128;          // valid: j <= lim
            float v[8];
            float mx = -FLT_MAX;
            #pragma unroll
            for (int u = 0; u < 8; u++) {
                const int j = lane + u * 32;
                float s = sim[r * SIMLD + j];
                v[u] = (j <= lim) ? s : -FLT_MAX;
                mx = fmaxf(mx, v[u]);
            }
            #pragma unroll
            for (int off = 16; off; off >>= 1)
                mx = fmaxf(mx, __shfl_xor_sync(0xffffffffu, mx, off));
            float sum = 0.f;
            #pragma unroll
            for (int u = 0; u < 8; u++) {
                const int j = lane + u * 32;
                float e = (j <= lim) ? expf(v[u] - mx) : 0.f;
                v[u] = e;
                sum += e;
            }
            #pragma unroll
            for (int off = 16; off; off >>= 1)
                sum += __shfl_xor_sync(0xffffffffu, sum, off);
            const float inv = 1.f / sum;
            #pragma unroll
            for (int u = 0; u < 8; u++)
                sim[r * SIMLD + lane + u * 32] = v[u] * inv;
        }
    }
    __syncthreads();

    // ---- Phase B: out = attn @ k2  (128x1024, K=256) ----
    const int lkk = t >> 5;
    const int ln4 = (t & 31) * 4;
    for (int nc = 0; nc < 8; nc++) {
        const int n0 = nc * 128;
        float acc[8][8] = {};
        for (int kt = 0; kt < 256; kt += 8) {
            const int j   = kt + lkk;                 // key index 0..255
            const int tok = (w - 1) * WW + j;         // global token
            float4 b4 = make_float4(0.f, 0.f, 0.f, 0.f);
            if (tok >= 0)
                b4 = *(const float4*)&g_k[((size_t)b * NN + tok) * DD + n0 + ln4];
            Bs[lkk * TLD + ln4 + 0] = b4.x;
            Bs[lkk * TLD + ln4 + 1] = b4.y;
            Bs[lkk * TLD + ln4 + 2] = b4.z;
            Bs[lkk * TLD + ln4 + 3] = b4.w;

            __syncthreads();
            #pragma unroll
            for (int kk = 0; kk < 8; kk++) {
                float rA[8], rB[8];
                #pragma unroll
                for (int i = 0; i < 8; i++) rA[i] = sim[(ty * 8 + i) * SIMLD + kt + kk];
                #pragma unroll
                for (int jj = 0; jj < 8; jj++) rB[jj] = Bs[kk * TLD + tx * 8 + jj];
                #pragma unroll
                for (int i = 0; i < 8; i++)
                    #pragma unroll
                    for (int jj = 0; jj < 8; jj++)
                        acc[i][jj] = fmaf(rA[i], rB[jj], acc[i][jj]);
            }
            __syncthreads();
        }
        #pragma unroll
        for (int i = 0; i < 8; i++)
            #pragma unroll
            for (int jj = 0; jj < 8; jj++)
                g_ao[qbase + (size_t)(ty * 8 + i) * DD + n0 + tx * 8 + jj] = acc[i][jj];
    }
}

// ---------------------------------------------------------------------------
extern "C" void kernel_launch(void* const* d_in, const int* in_sizes, int n_in,
                              void* d_out, int out_size)
{
    (void)in_sizes; (void)n_in; (void)out_size;
    const float* x     = (const float*)d_in[0];   // [4,4096,1024]
    const float* w_qkv = (const float*)d_in[1];   // [1024,3072]
    const float* w_out = (const float*)d_in[2];   // [1024,1024]
    const float* b_out = (const float*)d_in[3];   // [1024]
    float* out = (float*)d_out;                   // [4,4096,1024]

    cudaFuncSetAttribute(attn_kernel,
                         cudaFuncAttributeMaxDynamicSharedMemorySize,
                         ATTN_SMEM_BYTES);

    // 1) qk = x @ w_qkv[:, :2048]  (v columns are dead code in the reference)
    gemm_kernel<0><<<dim3(2048 / 128, MTOT / 128), 256>>>(x, w_qkv, nullptr, nullptr);

    // 2) windowed causal attention (values == keys per the reference bug)
    attn_kernel<<<dim3(NWIN, BB), 256, ATTN_SMEM_BYTES>>>();

    // 3) out = attn_out @ w_out + b_out
    gemm_kernel<1><<<dim3(1024 / 128, MTOT / 128), 256>>>(nullptr, w_out, b_out, out);
}

// round 7
// speedup vs baseline: 2.2563x; 2.2563x over previous
#include <cuda_runtime.h>
#include <cuda_bf16.h>
#include <cstdint>
#include <math.h>
#include <float.h>

#define BB   4
#define NN   4096
#define DD   1024
#define WW   128
#define NWIN (NN / WW)          // 32
#define MTOT (BB * NN)          // 16384

// ---------------------------------------------------------------------------
// bf16 hi/lo split scratch. NOTE: these are ONLY ever referenced from device
// code (never passed as kernel args from host — host-side &symbol is the
// shadow copy, and GB300's ATS makes writes to it silently land in host mem).
// ---------------------------------------------------------------------------
__device__ __nv_bfloat16 g_x_hi  [(size_t)MTOT * DD];
__device__ __nv_bfloat16 g_x_lo  [(size_t)MTOT * DD];
__device__ __nv_bfloat16 g_wqk_hi[(size_t)2048 * DD];   // [n][k] = w_qkv[k][n]
__device__ __nv_bfloat16 g_wqk_lo[(size_t)2048 * DD];
__device__ __nv_bfloat16 g_wo_hi [(size_t)1024 * DD];   // [n][k] = w_out[k][n]
__device__ __nv_bfloat16 g_wo_lo [(size_t)1024 * DD];
__device__ __nv_bfloat16 g_q_hi  [(size_t)MTOT * DD];
__device__ __nv_bfloat16 g_q_lo  [(size_t)MTOT * DD];
__device__ __nv_bfloat16 g_k_hi  [(size_t)MTOT * DD];
__device__ __nv_bfloat16 g_k_lo  [(size_t)MTOT * DD];
__device__ __nv_bfloat16 g_kT_hi [(size_t)BB * DD * NN]; // [b][d][t]
__device__ __nv_bfloat16 g_kT_lo [(size_t)BB * DD * NN];
__device__ __nv_bfloat16 g_attn_hi[(size_t)MTOT * 256];  // unnormalized exp
__device__ __nv_bfloat16 g_attn_lo[(size_t)MTOT * 256];
__device__ __nv_bfloat16 g_ao_hi [(size_t)MTOT * DD];
__device__ __nv_bfloat16 g_ao_lo [(size_t)MTOT * DD];
__device__ float         g_invsum[MTOT];

// ---------------------------------------------------------------------------
// mma.sync m16n8k16 bf16 (canonical fragment layouts)
// ---------------------------------------------------------------------------
__device__ __forceinline__ void mma16816(float* c, const uint32_t* a, const uint32_t* b) {
    asm volatile(
        "mma.sync.aligned.m16n8k16.row.col.f32.bf16.bf16.f32 "
        "{%0,%1,%2,%3}, {%4,%5,%6,%7}, {%8,%9}, {%0,%1,%2,%3};"
        : "+f"(c[0]), "+f"(c[1]), "+f"(c[2]), "+f"(c[3])
        : "r"(a[0]), "r"(a[1]), "r"(a[2]), "r"(a[3]), "r"(b[0]), "r"(b[1]));
}

__device__ __forceinline__ void f2bf_split(float v, __nv_bfloat16& hi, __nv_bfloat16& lo) {
    hi = __float2bfloat16(v);
    lo = __float2bfloat16(v - __bfloat162float(hi));
}

// smem per buffer: K-chunk 16 -> 32B data + 16B pad = 48B row stride.
#define RS    48
#define A_HI  0
#define A_LO  6144
#define B_HI  12288
#define B_LO  24576
#define BUFB  36864
#define SMEMB 131584            // stg 128*257*4 aliases the two buffers

struct StgRegs { uint4 aH, aL, bH0, bL0, bH1, bL1; };

// load one K-chunk (16 elems) of A[128]x16 + B[256]x16 (hi+lo) into registers
__device__ __forceinline__ void ld_chunk(
    StgRegs& R, int c, int stage, int w,
    const __nv_bfloat16* Ah, const __nv_bfloat16* Al,
    const __nv_bfloat16* Bh, const __nv_bfloat16* Bl,
    long long aBase, long long bBase, int Astr, int Bstr, int t)
{
    const int kE = c * 16;
    {
        const int r = t >> 1, sg = t & 1;
        const long long off = aBase + (long long)r * Astr + kE + sg * 8;
        R.aH = *(const uint4*)(Ah + off);
        R.aL = *(const uint4*)(Al + off);
    }
    const uint4 z = make_uint4(0u, 0u, 0u, 0u);
    {
        const int r = t >> 1, sg = t & 1;           // B rows 0..127
        bool v = true;
        if (stage == 1) v = (w > 0);                // rows <128 = prev window
        if (stage == 2) v = (w > 0) || (c >= 8);
        if (v) {
            const long long off = bBase + (long long)r * Bstr + kE + sg * 8;
            R.bH0 = *(const uint4*)(Bh + off);
            R.bL0 = *(const uint4*)(Bl + off);
        } else { R.bH0 = z; R.bL0 = z; }
    }
    {
        const int idx = t + 256;                    // B rows 128..255
        const int r = idx >> 1, sg = idx & 1;
        bool v = true;
        if (stage == 2) v = (w > 0) || (c >= 8);
        if (v) {
            const long long off = bBase + (long long)r * Bstr + kE + sg * 8;
            R.bH1 = *(const uint4*)(Bh + off);
            R.bL1 = *(const uint4*)(Bl + off);
        } else { R.bH1 = z; R.bL1 = z; }
    }
}

__device__ __forceinline__ void st_chunk(char* sm, int s, const StgRegs& R, int t)
{
    char* buf = sm + (size_t)s * BUFB;
    {
        const int o = (t >> 1) * RS + (t & 1) * 16;
        *(uint4*)(buf + A_HI + o) = R.aH;
        *(uint4*)(buf + A_LO + o) = R.aL;
        *(uint4*)(buf + B_HI + o) = R.bH0;
        *(uint4*)(buf + B_LO + o) = R.bL0;
    }
    {
        const int idx = t + 256;
        const int o = (idx >> 1) * RS + (idx & 1) * 16;
        *(uint4*)(buf + B_HI + o) = R.bH1;
        *(uint4*)(buf + B_LO + o) = R.bL1;
    }
}

// one K-chunk (k=16): bf16x3 (AhBh + AhBl + AlBh), warp tile 64x64
__device__ __forceinline__ void compute_chunk(
    char* sm, int s, int wm, int wn, int g, int tg, float (&acc)[4][8][4])
{
    char* buf = sm + (size_t)s * BUFB;
    const int aOff = (wm * 64 + g) * RS + tg * 4;
    const int bOff = (wn * 64 + g) * RS + tg * 4;

    uint32_t A[4][4], B0[8][2], B1[8][2];
    #pragma unroll
    for (int fm = 0; fm < 4; fm++) {
        const int o = aOff + fm * 768;               // 16 rows * 48B
        A[fm][0] = *(const uint32_t*)(buf + A_HI + o);
        A[fm][1] = *(const uint32_t*)(buf + A_HI + o + 384);   // +8 rows
        A[fm][2] = *(const uint32_t*)(buf + A_HI + o + 16);    // +8 k
        A[fm][3] = *(const uint32_t*)(buf + A_HI + o + 400);
    }
    #pragma unroll
    for (int fn = 0; fn < 8; fn++) {
        const int o = bOff + fn * 384;               // 8 rows * 48B
        B0[fn][0] = *(const uint32_t*)(buf + B_HI + o);
        B0[fn][1] = *(const uint32_t*)(buf + B_HI + o + 16);
    }
    #pragma unroll
    for (int fm = 0; fm < 4; fm++)
        #pragma unroll
        for (int fn = 0; fn < 8; fn++)
            mma16816(acc[fm][fn], A[fm], B0[fn]);    // Ah*Bh
    #pragma unroll
    for (int fn = 0; fn < 8; fn++) {
        const int o = bOff + fn * 384;
        B1[fn][0] = *(const uint32_t*)(buf + B_LO + o);
        B1[fn][1] = *(const uint32_t*)(buf + B_LO + o + 16);
    }
    #pragma unroll
    for (int fm = 0; fm < 4; fm++)
        #pragma unroll
        for (int fn = 0; fn < 8; fn++)
            mma16816(acc[fm][fn], A[fm], B1[fn]);    // Ah*Bl
    #pragma unroll
    for (int fm = 0; fm < 4; fm++) {
        const int o = aOff + fm * 768;
        A[fm][0] = *(const uint32_t*)(buf + A_LO + o);
        A[fm][1] = *(const uint32_t*)(buf + A_LO + o + 384);
        A[fm][2] = *(const uint32_t*)(buf + A_LO + o + 16);
        A[fm][3] = *(const uint32_t*)(buf + A_LO + o + 400);
    }
    #pragma unroll
    for (int fm = 0; fm < 4; fm++)
        #pragma unroll
        for (int fn = 0; fn < 8; fn++)
            mma16816(acc[fm][fn], A[fm], B0[fn]);    // Al*Bh
}

// ---------------------------------------------------------------------------
// Unified GEMM: D[128,256] = A[128,K] @ B[256,K]^T via mma.sync bf16x3.
// stage 0: QKV   A=x        B=wqkT        K=1024  epi: split into g_q / g_k
// stage 1: QK^T  A=q(win)   B=k(win-1,w)  K=1024  epi: softmax -> attn+invsum
// stage 2: A*V   A=attn     B=kT          K=256   epi: *invsum -> g_ao
// stage 3: OUT   A=ao       B=woT         K=1024  epi: +bias -> d_out (fp32)
// ---------------------------------------------------------------------------
__global__ void __launch_bounds__(256, 1) mma_gemm(int stage,
                                                   float* __restrict__ dOut,
                                                   const float* __restrict__ bias)
{
    extern __shared__ char sm[];
    const int t = threadIdx.x;
    const int lane = t & 31, wid = t >> 5;
    const int wm = wid >> 2, wn = wid & 3;
    const int g = lane >> 2, tg = lane & 3;

    int m0 = 0, n0 = 0, b = 0, w = 0;
    if (stage == 0)      { n0 = blockIdx.x * 256; m0 = blockIdx.y * 128; }
    else if (stage == 1) { w = blockIdx.x; b = blockIdx.y; }
    else if (stage == 2) { n0 = blockIdx.x * 256; w = blockIdx.y; b = blockIdx.z; }
    else                 { n0 = blockIdx.x * 256; m0 = blockIdx.y * 128; }

    const int NCH = (stage == 2) ? 16 : 64;

    const __nv_bfloat16 *Ah, *Al, *Bh, *Bl;
    long long aBase, bBase;
    int Astr, Bstr;
    if (stage == 0) {
        Ah = g_x_hi;  Al = g_x_lo;  Bh = g_wqk_hi; Bl = g_wqk_lo;
        aBase = (long long)m0 * DD; bBase = (long long)n0 * DD; Astr = DD; Bstr = DD;
    } else if (stage == 1) {
        Ah = g_q_hi;  Al = g_q_lo;  Bh = g_k_hi;   Bl = g_k_lo;
        aBase = ((long long)b * NN + (long long)w * WW) * DD;
        bBase = ((long long)b * NN + (long long)(w - 1) * WW) * DD;
        Astr = DD; Bstr = DD;
    } else if (stage == 2) {
        Ah = g_attn_hi; Al = g_attn_lo; Bh = g_kT_hi; Bl = g_kT_lo;
        aBase = ((long long)(b * NWIN + w) * WW) * 256;
        bBase = ((long long)(b * DD + n0)) * NN + (long long)(w - 1) * WW;
        Astr = 256; Bstr = NN;
    } else {
        Ah = g_ao_hi; Al = g_ao_lo; Bh = g_wo_hi; Bl = g_wo_lo;
        aBase = (long long)m0 * DD; bBase = (long long)n0 * DD; Astr = DD; Bstr = DD;
    }

    float acc[4][8][4];
    #pragma unroll
    for (int i = 0; i < 4; i++)
        #pragma unroll
        for (int j = 0; j < 8; j++)
            #pragma unroll
            for (int e = 0; e < 4; e++) acc[i][j][e] = 0.f;

    StgRegs R;
    ld_chunk(R, 0, stage, w, Ah, Al, Bh, Bl, aBase, bBase, Astr, Bstr, t);
    st_chunk(sm, 0, R, t);

    for (int c = 0; c < NCH; c++) {
        __syncthreads();                       // buffer c&1 visible
        if (c + 1 < NCH)
            ld_chunk(R, c + 1, stage, w, Ah, Al, Bh, Bl, aBase, bBase, Astr, Bstr, t);
        compute_chunk(sm, c & 1, wm, wn, g, tg, acc);
        if (c + 1 < NCH)
            st_chunk(sm, (c + 1) & 1, R, t);   // other buffer; synced next iter
    }
    __syncthreads();

    // ---- stage D[128,256] into smem [128][257] fp32 (aliases buffers) ----
    float* stg = (float*)sm;
    #pragma unroll
    for (int fm = 0; fm < 4; fm++) {
        const int r0 = wm * 64 + fm * 16 + g;
        #pragma unroll
        for (int fn = 0; fn < 8; fn++) {
            const int c0 = wn * 64 + fn * 8 + tg * 2;
            stg[r0 * 257 + c0]           = acc[fm][fn][0];
            stg[r0 * 257 + c0 + 1]       = acc[fm][fn][1];
            stg[(r0 + 8) * 257 + c0]     = acc[fm][fn][2];
            stg[(r0 + 8) * 257 + c0 + 1] = acc[fm][fn][3];
        }
    }
    __syncthreads();

    // ---- stage-specific epilogue ----
    const int wg = wid;
    if (stage == 0) {
        const bool isQ = (n0 < 1024);
        __nv_bfloat16* dh = isQ ? g_q_hi : g_k_hi;
        __nv_bfloat16* dl = isQ ? g_q_lo : g_k_lo;
        const int nq = isQ ? n0 : (n0 - 1024);
        #pragma unroll 4
        for (int r = 0; r < 128; r++) {
            float v = stg[r * 257 + t];
            __nv_bfloat16 hi, lo; f2bf_split(v, hi, lo);
            size_t o = (size_t)(m0 + r) * DD + nq + t;
            dh[o] = hi; dl[o] = lo;
        }
    } else if (stage == 1) {
        const int rowbase = (b * NWIN + w) * WW;
        for (int rr = 0; rr < 16; rr++) {
            const int r = wg * 16 + rr;
            float vv[8];
            float mx = -FLT_MAX;
            #pragma unroll
            for (int u = 0; u < 8; u++) {
                int j = lane + u * 32;
                float sc = stg[r * 257 + j] * 0.03125f;
                vv[u] = (j <= r + 128) ? sc : -FLT_MAX;
                mx = fmaxf(mx, vv[u]);
            }
            #pragma unroll
            for (int off = 16; off; off >>= 1)
                mx = fmaxf(mx, __shfl_xor_sync(0xffffffffu, mx, off));
            float sum = 0.f;
            #pragma unroll
            for (int u = 0; u < 8; u++) {
                int j = lane + u * 32;
                float e = (j <= r + 128) ? expf(vv[u] - mx) : 0.f;
                sum += e;
                __nv_bfloat16 hi, lo; f2bf_split(e, hi, lo);
                size_t o = (size_t)(rowbase + r) * 256 + j;
                g_attn_hi[o] = hi; g_attn_lo[o] = lo;
            }
            #pragma unroll
            for (int off = 16; off; off >>= 1)
                sum += __shfl_xor_sync(0xffffffffu, sum, off);
            if (lane == 0) g_invsum[rowbase + r] = 1.f / sum;
        }
    } else if (stage == 2) {
        const int rowbase = (b * NWIN + w) * WW;
        #pragma unroll 4
        for (int r = 0; r < 128; r++) {
            float v = stg[r * 257 + t] * g_invsum[rowbase + r];
            __nv_bfloat16 hi, lo; f2bf_split(v, hi, lo);
            size_t o = ((size_t)b * NN + (size_t)w * WW + r) * DD + n0 + t;
            g_ao_hi[o] = hi; g_ao_lo[o] = lo;
        }
    } else {
        const float bv = bias[n0 + t];
        #pragma unroll 4
        for (int r = 0; r < 128; r++)
            dOut[(size_t)(m0 + r) * DD + n0 + t] = stg[r * 257 + t] + bv;
    }
}

// ---------------------------------------------------------------------------
// Converters — destinations are device globals referenced IN DEVICE CODE ONLY
// ---------------------------------------------------------------------------
__global__ void convert_x_kernel(const float* __restrict__ x)
{
    size_t i = ((size_t)blockIdx.x * blockDim.x + threadIdx.x) * 4;
    float4 v = *(const float4*)(x + i);
    float vals[4] = { v.x, v.y, v.z, v.w };
    #pragma unroll
    for (int j = 0; j < 4; j++) {
        __nv_bfloat16 hi, lo; f2bf_split(vals[j], hi, lo);
        g_x_hi[i + j] = hi;
        g_x_lo[i + j] = lo;
    }
}

// dst[n][k] = src[k][n], bf16 hi/lo split; which: 0 -> wqk, 1 -> wo.
// grid: (N/32, 1024/32), block (32,8)
__global__ void transpose_convert_w(const float* __restrict__ src, int ld, int which)
{
    __nv_bfloat16* dh = (which == 0) ? g_wqk_hi : g_wo_hi;
    __nv_bfloat16* dl = (which == 0) ? g_wqk_lo : g_wo_lo;
    __shared__ float sh[32][33];
    const int n0 = blockIdx.x * 32, k0 = blockIdx.y * 32;
    const int tx = threadIdx.x, ty = threadIdx.y;
    #pragma unroll
    for (int i = 0; i < 4; i++)
        sh[ty + 8 * i][tx] = src[(size_t)(k0 + ty + 8 * i) * ld + n0 + tx];
    __syncthreads();
    #pragma unroll
    for (int i = 0; i < 4; i++) {
        float v = sh[tx][ty + 8 * i];
        int n = n0 + ty + 8 * i, k = k0 + tx;
        __nv_bfloat16 hi, lo; f2bf_split(v, hi, lo);
        dh[(size_t)n * DD + k] = hi;
        dl[(size_t)n * DD + k] = lo;
    }
}

// kT[b][d][t] = k[b][t][d]. grid: (1024/32, 4096/32, 4), block (32,8)
__global__ void transpose_k_kernel()
{
    __shared__ __nv_bfloat16 shh[32][34];
    __shared__ __nv_bfloat16 shl[32][34];
    const int d0 = blockIdx.x * 32, t0 = blockIdx.y * 32, b = blockIdx.z;
    const int tx = threadIdx.x, ty = threadIdx.y;
    #pragma unroll
    for (int i = 0; i < 4; i++) {
        int tok = t0 + ty + 8 * i;
        size_t o = ((size_t)b * NN + tok) * DD + d0 + tx;
        shh[ty + 8 * i][tx] = g_k_hi[o];
        shl[ty + 8 * i][tx] = g_k_lo[o];
    }
    __syncthreads();
    #pragma unroll
    for (int i = 0; i < 4; i++) {
        int d = d0 + ty + 8 * i;
        size_t o = ((size_t)b * DD + d) * NN + t0 + tx;
        g_kT_hi[o] = shh[tx][ty + 8 * i];
        g_kT_lo[o] = shl[tx][ty + 8 * i];
    }
}

// ---------------------------------------------------------------------------
extern "C" void kernel_launch(void* const* d_in, const int* in_sizes, int n_in,
                              void* d_out, int out_size)
{
    (void)in_sizes; (void)n_in; (void)out_size;
    const float* x     = (const float*)d_in[0];   // [4,4096,1024]
    const float* w_qkv = (const float*)d_in[1];   // [1024,3072]
    const float* w_out = (const float*)d_in[2];   // [1024,1024]
    const float* b_out = (const float*)d_in[3];   // [1024]
    float* out = (float*)d_out;                   // [4,4096,1024]

    cudaFuncSetAttribute(mma_gemm, cudaFuncAttributeMaxDynamicSharedMemorySize, SMEMB);

    // 1) split inputs into bf16 hi/lo
    convert_x_kernel<<<MTOT * DD / 1024, 256>>>(x);
    transpose_convert_w<<<dim3(64, 32), dim3(32, 8)>>>(w_qkv, 3072, 0);
    transpose_convert_w<<<dim3(32, 32), dim3(32, 8)>>>(w_out, 1024, 1);

    // 2) qk = x @ w_qkv[:, :2048]   (mma.sync bf16x3)
    mma_gemm<<<dim3(8, 128), 256, SMEMB>>>(0, nullptr, nullptr);

    // 3) k transposed per batch for the attn*V GEMM
    transpose_k_kernel<<<dim3(32, 128, 4), dim3(32, 8)>>>();

    // 4) sim = q @ k2^T, softmax fused (unnormalized exp + invsum)
    mma_gemm<<<dim3(NWIN, BB), 256, SMEMB>>>(1, nullptr, nullptr);

    // 5) ao = attn @ k2 (values == keys per reference bug)
    mma_gemm<<<dim3(4, NWIN, BB), 256, SMEMB>>>(2, nullptr, nullptr);

    // 6) out = ao @ w_out + b_out
    mma_gemm<<<dim3(4, 128), 256, SMEMB>>>(3, out, b_out);
}

// round 8
// speedup vs baseline: 2.7978x; 1.2400x over previous
#include <cuda_runtime.h>
#include <cuda_bf16.h>
#include <cstdint>
#include <math.h>
#include <float.h>

#define BB   4
#define NN   4096
#define DD   1024
#define WW   128
#define NWIN (NN / WW)          // 32
#define MTOT (BB * NN)          // 16384

// ---------------------------------------------------------------------------
// bf16 hi/lo split scratch. ONLY referenced from device code — NEVER passed
// as kernel args from host (host-side &symbol is the shadow copy; GB300 ATS
// makes writes to it silently land in host memory).
// ---------------------------------------------------------------------------
__device__ __nv_bfloat16 g_x_hi  [(size_t)MTOT * DD];
__device__ __nv_bfloat16 g_x_lo  [(size_t)MTOT * DD];
__device__ __nv_bfloat16 g_wqk_hi[(size_t)2048 * DD];   // [n][k] = w_qkv[k][n]
__device__ __nv_bfloat16 g_wqk_lo[(size_t)2048 * DD];
__device__ __nv_bfloat16 g_wo_hi [(size_t)1024 * DD];   // [n][k] = w_out[k][n]
__device__ __nv_bfloat16 g_wo_lo [(size_t)1024 * DD];
__device__ __nv_bfloat16 g_q_hi  [(size_t)MTOT * DD];
__device__ __nv_bfloat16 g_q_lo  [(size_t)MTOT * DD];
__device__ __nv_bfloat16 g_k_hi  [(size_t)MTOT * DD];
__device__ __nv_bfloat16 g_k_lo  [(size_t)MTOT * DD];
__device__ __nv_bfloat16 g_kT_hi [(size_t)BB * DD * NN]; // [b][d][t]
__device__ __nv_bfloat16 g_kT_lo [(size_t)BB * DD * NN];
__device__ __nv_bfloat16 g_attn_hi[(size_t)MTOT * 256];  // unnormalized exp
__device__ __nv_bfloat16 g_attn_lo[(size_t)MTOT * 256];
__device__ __nv_bfloat16 g_ao_hi [(size_t)MTOT * DD];
__device__ __nv_bfloat16 g_ao_lo [(size_t)MTOT * DD];
__device__ float         g_invsum[MTOT];

// ---------------------------------------------------------------------------
// primitives
// ---------------------------------------------------------------------------
__device__ __forceinline__ uint32_t smem_u32(const void* p) {
    uint32_t a;
    asm("{ .reg .u64 t; cvta.to.shared.u64 t, %1; cvt.u32.u64 %0, t; }"
        : "=r"(a) : "l"(p));
    return a;
}

__device__ __forceinline__ void mma16816(float* c, const uint32_t* a, const uint32_t* b) {
    asm volatile(
        "mma.sync.aligned.m16n8k16.row.col.f32.bf16.bf16.f32 "
        "{%0,%1,%2,%3}, {%4,%5,%6,%7}, {%8,%9}, {%0,%1,%2,%3};"
        : "+f"(c[0]), "+f"(c[1]), "+f"(c[2]), "+f"(c[3])
        : "r"(a[0]), "r"(a[1]), "r"(a[2]), "r"(a[3]), "r"(b[0]), "r"(b[1]));
}

__device__ __forceinline__ void ldsm_x4(uint32_t& d0, uint32_t& d1,
                                        uint32_t& d2, uint32_t& d3, uint32_t a) {
    asm volatile("ldmatrix.sync.aligned.m8n8.x4.shared.b16 {%0,%1,%2,%3}, [%4];"
                 : "=r"(d0), "=r"(d1), "=r"(d2), "=r"(d3) : "r"(a));
}

__device__ __forceinline__ void cp16(uint32_t dst, const void* src) {
    asm volatile("cp.async.cg.shared.global [%0], [%1], 16;"
                 :: "r"(dst), "l"(src) : "memory");
}
#define CP_COMMIT() asm volatile("cp.async.commit_group;" ::: "memory")
#define CP_WAIT2()  asm volatile("cp.async.wait_group 2;" ::: "memory")

__device__ __forceinline__ void f2bf_split(float v, __nv_bfloat16& hi, __nv_bfloat16& lo) {
    hi = __float2bfloat16(v);
    lo = __float2bfloat16(v - __bfloat162float(hi));
}

// smem per buffer: K-chunk 16 -> 32B data + 16B pad = 48B row stride.
#define RS    48
#define A_HI  0
#define A_LO  6144
#define B_HI  12288
#define B_LO  24576
#define BUFB  36864
#define NBUF  4
#define SMEMB (NBUF * BUFB)     // 147456; stg 128*257*4=131584 aliases it

// ---------------------------------------------------------------------------
// async chunk loader (A[128]x16 + B[256]x16, hi+lo), masked blocks zero-stored
// ---------------------------------------------------------------------------
__device__ __forceinline__ void load_chunk_async(
    char* sm, uint32_t smb, int cc, int bufIdx, int stage, int w, int t,
    const __nv_bfloat16* Ah, const __nv_bfloat16* Al,
    const __nv_bfloat16* Bh, const __nv_bfloat16* Bl,
    long long aBase, long long bBase, int Astr, int Bstr)
{
    const int kE = cc * 16;
    const uint32_t bo = (uint32_t)bufIdx * BUFB;
    const int r = t >> 1, sg = t & 1;
    const uint4 z = make_uint4(0u, 0u, 0u, 0u);
    // A
    {
        const long long off = aBase + (long long)r * Astr + kE + sg * 8;
        const uint32_t d = smb + bo + A_HI + r * RS + sg * 16;
        cp16(d, Ah + off);
        cp16(d + (A_LO - A_HI), Al + off);
    }
    // B rows 0..127
    {
        bool v = true;
        if (stage == 1) v = (w > 0);
        if (stage == 2) v = (w > 0) || (cc >= 8);
        const int o = B_HI + r * RS + sg * 16;
        if (v) {
            const long long off = bBase + (long long)r * Bstr + kE + sg * 8;
            cp16(smb + bo + o, Bh + off);
            cp16(smb + bo + o + (B_LO - B_HI), Bl + off);
        } else {
            *(uint4*)(sm + bo + o) = z;
            *(uint4*)(sm + bo + o + (B_LO - B_HI)) = z;
        }
    }
    // B rows 128..255
    {
        const int r2 = r + 128;
        bool v = true;
        if (stage == 2) v = (w > 0) || (cc >= 8);
        const int o = B_HI + r2 * RS + sg * 16;
        if (v) {
            const long long off = bBase + (long long)r2 * Bstr + kE + sg * 8;
            cp16(smb + bo + o, Bh + off);
            cp16(smb + bo + o + (B_LO - B_HI), Bl + off);
        } else {
            *(uint4*)(sm + bo + o) = z;
            *(uint4*)(sm + bo + o + (B_LO - B_HI)) = z;
        }
    }
}

// ---------------------------------------------------------------------------
// one K-chunk (k=16): bf16x3 (AhBh + AhBl + AlBh) via ldmatrix fragments
// ---------------------------------------------------------------------------
__device__ __forceinline__ void compute_chunk(
    uint32_t bufAdd, const uint32_t* aAddr, const uint32_t* bAddr,
    float (&acc)[4][8][4])
{
    uint32_t A[4][4], B0[8][2], B1[8][2];
    #pragma unroll
    for (int fm = 0; fm < 4; fm++)
        ldsm_x4(A[fm][0], A[fm][1], A[fm][2], A[fm][3], aAddr[fm] + bufAdd);
    #pragma unroll
    for (int p = 0; p < 4; p++)
        ldsm_x4(B0[2*p][0], B0[2*p][1], B0[2*p+1][0], B0[2*p+1][1],
                bAddr[p] + bufAdd);
    #pragma unroll
    for (int fm = 0; fm < 4; fm++)
        #pragma unroll
        for (int fn = 0; fn < 8; fn++)
            mma16816(acc[fm][fn], A[fm], B0[fn]);    // Ah*Bh
    #pragma unroll
    for (int p = 0; p < 4; p++)
        ldsm_x4(B1[2*p][0], B1[2*p][1], B1[2*p+1][0], B1[2*p+1][1],
                bAddr[p] + bufAdd + (B_LO - B_HI));
    #pragma unroll
    for (int fm = 0; fm < 4; fm++)
        #pragma unroll
        for (int fn = 0; fn < 8; fn++)
            mma16816(acc[fm][fn], A[fm], B1[fn]);    // Ah*Bl
    #pragma unroll
    for (int fm = 0; fm < 4; fm++)
        ldsm_x4(A[fm][0], A[fm][1], A[fm][2], A[fm][3],
                aAddr[fm] + bufAdd + (A_LO - A_HI));
    #pragma unroll
    for (int fm = 0; fm < 4; fm++)
        #pragma unroll
        for (int fn = 0; fn < 8; fn++)
            mma16816(acc[fm][fn], A[fm], B0[fn]);    // Al*Bh
}

// ---------------------------------------------------------------------------
// Unified GEMM: D[128,256] = A[128,K] @ B[256,K]^T via mma.sync bf16x3.
// stage 0: QKV   A=x        B=wqkT        K=1024  epi: split into g_q / g_k
// stage 1: QK^T  A=q(win)   B=k(win-1,w)  K=1024  epi: softmax -> attn+invsum
// stage 2: A*V   A=attn     B=kT          K=256   epi: *invsum -> g_ao
// stage 3: OUT   A=ao       B=woT         K=1024  epi: +bias -> d_out (fp32)
// ---------------------------------------------------------------------------
__global__ void __launch_bounds__(256, 1) mma_gemm(int stage,
                                                   float* __restrict__ dOut,
                                                   const float* __restrict__ bias)
{
    extern __shared__ char sm[];
    const uint32_t smb = smem_u32(sm);
    const int t = threadIdx.x;
    const int lane = t & 31, wid = t >> 5;
    const int wm = wid >> 2, wn = wid & 3;
    const int g = lane >> 2, tg = lane & 3;

    int m0 = 0, n0 = 0, b = 0, w = 0;
    if (stage == 0)      { n0 = blockIdx.x * 256; m0 = blockIdx.y * 128; }
    else if (stage == 1) { w = blockIdx.x; b = blockIdx.y; }
    else if (stage == 2) { n0 = blockIdx.x * 256; w = blockIdx.y; b = blockIdx.z; }
    else                 { n0 = blockIdx.x * 256; m0 = blockIdx.y * 128; }

    const int NCH = (stage == 2) ? 16 : 64;

    const __nv_bfloat16 *Ah, *Al, *Bh, *Bl;
    long long aBase, bBase;
    int Astr, Bstr;
    if (stage == 0) {
        Ah = g_x_hi;  Al = g_x_lo;  Bh = g_wqk_hi; Bl = g_wqk_lo;
        aBase = (long long)m0 * DD; bBase = (long long)n0 * DD; Astr = DD; Bstr = DD;
    } else if (stage == 1) {
        Ah = g_q_hi;  Al = g_q_lo;  Bh = g_k_hi;   Bl = g_k_lo;
        aBase = ((long long)b * NN + (long long)w * WW) * DD;
        bBase = ((long long)b * NN + (long long)(w - 1) * WW) * DD;
        Astr = DD; Bstr = DD;
    } else if (stage == 2) {
        Ah = g_attn_hi; Al = g_attn_lo; Bh = g_kT_hi; Bl = g_kT_lo;
        aBase = ((long long)(b * NWIN + w) * WW) * 256;
        bBase = ((long long)(b * DD + n0)) * NN + (long long)(w - 1) * WW;
        Astr = 256; Bstr = NN;
    } else {
        Ah = g_ao_hi; Al = g_ao_lo; Bh = g_wo_hi; Bl = g_wo_lo;
        aBase = (long long)m0 * DD; bBase = (long long)n0 * DD; Astr = DD; Bstr = DD;
    }

    // ldmatrix lane addresses (buffer 0; add bufAdd per chunk)
    uint32_t aAddr[4], bAddr[4];
    {
        const int rowA = lane & 15;
        const int khA  = (lane >> 4) * 16;
        #pragma unroll
        for (int fm = 0; fm < 4; fm++)
            aAddr[fm] = smb + A_HI + (uint32_t)((wm * 64 + fm * 16 + rowA) * RS + khA);
        const int rowB = (lane & 7) + ((lane >> 4) & 1) * 8;
        const int khB  = ((lane >> 3) & 1) * 16;
        #pragma unroll
        for (int p = 0; p < 4; p++)
            bAddr[p] = smb + B_HI + (uint32_t)((wn * 64 + p * 16 + rowB) * RS + khB);
    }

    float acc[4][8][4];
    #pragma unroll
    for (int i = 0; i < 4; i++)
        #pragma unroll
        for (int j = 0; j < 8; j++)
            #pragma unroll
            for (int e = 0; e < 4; e++) acc[i][j][e] = 0.f;

    // prologue: 3 chunks in flight
    load_chunk_async(sm, smb, 0, 0, stage, w, t, Ah, Al, Bh, Bl, aBase, bBase, Astr, Bstr);
    CP_COMMIT();
    load_chunk_async(sm, smb, 1, 1, stage, w, t, Ah, Al, Bh, Bl, aBase, bBase, Astr, Bstr);
    CP_COMMIT();
    load_chunk_async(sm, smb, 2, 2, stage, w, t, Ah, Al, Bh, Bl, aBase, bBase, Astr, Bstr);
    CP_COMMIT();

    #pragma unroll 1
    for (int c = 0; c < NCH; c++) {
        CP_WAIT2();                    // chunk c's group retired
        __syncthreads();               // all threads' cp.async for chunk c visible
        compute_chunk((uint32_t)((c & 3) * BUFB), aAddr, bAddr, acc);
        const int cc = c + 3;
        if (cc < NCH)
            load_chunk_async(sm, smb, cc, cc & 3, stage, w, t,
                             Ah, Al, Bh, Bl, aBase, bBase, Astr, Bstr);
        CP_COMMIT();                   // empty group when cc >= NCH keeps FIFO exact
    }
    __syncthreads();

    // ---- stage D[128,256] into smem [128][257] fp32 (aliases buffers) ----
    float* stg = (float*)sm;
    #pragma unroll
    for (int fm = 0; fm < 4; fm++) {
        const int r0 = wm * 64 + fm * 16 + g;
        #pragma unroll
        for (int fn = 0; fn < 8; fn++) {
            const int c0 = wn * 64 + fn * 8 + tg * 2;
            stg[r0 * 257 + c0]           = acc[fm][fn][0];
            stg[r0 * 257 + c0 + 1]       = acc[fm][fn][1];
            stg[(r0 + 8) * 257 + c0]     = acc[fm][fn][2];
            stg[(r0 + 8) * 257 + c0 + 1] = acc[fm][fn][3];
        }
    }
    __syncthreads();

    // ---- stage-specific epilogue ----
    const int wg = wid;
    if (stage == 0) {
        const bool isQ = (n0 < 1024);
        __nv_bfloat16* dh = isQ ? g_q_hi : g_k_hi;
        __nv_bfloat16* dl = isQ ? g_q_lo : g_k_lo;
        const int nq = isQ ? n0 : (n0 - 1024);
        #pragma unroll 4
        for (int r = 0; r < 128; r++) {
            float v = stg[r * 257 + t];
            __nv_bfloat16 hi, lo; f2bf_split(v, hi, lo);
            size_t o = (size_t)(m0 + r) * DD + nq + t;
            dh[o] = hi; dl[o] = lo;
        }
    } else if (stage == 1) {
        const int rowbase = (b * NWIN + w) * WW;
        for (int rr = 0; rr < 16; rr++) {
            const int r = wg * 16 + rr;
            float vv[8];
            float mx = -FLT_MAX;
            #pragma unroll
            for (int u = 0; u < 8; u++) {
                int j = lane + u * 32;
                float sc = stg[r * 257 + j] * 0.03125f;
                vv[u] = (j <= r + 128) ? sc : -FLT_MAX;
                mx = fmaxf(mx, vv[u]);
            }
            #pragma unroll
            for (int off = 16; off; off >>= 1)
                mx = fmaxf(mx, __shfl_xor_sync(0xffffffffu, mx, off));
            float sum = 0.f;
            #pragma unroll
            for (int u = 0; u < 8; u++) {
                int j = lane + u * 32;
                float e = (j <= r + 128) ? expf(vv[u] - mx) : 0.f;
                sum += e;
                __nv_bfloat16 hi, lo; f2bf_split(e, hi, lo);
                size_t o = (size_t)(rowbase + r) * 256 + j;
                g_attn_hi[o] = hi; g_attn_lo[o] = lo;
            }
            #pragma unroll
            for (int off = 16; off; off >>= 1)
                sum += __shfl_xor_sync(0xffffffffu, sum, off);
            if (lane == 0) g_invsum[rowbase + r] = 1.f / sum;
        }
    } else if (stage == 2) {
        const int rowbase = (b * NWIN + w) * WW;
        #pragma unroll 4
        for (int r = 0; r < 128; r++) {
            float v = stg[r * 257 + t] * g_invsum[rowbase + r];
            __nv_bfloat16 hi, lo; f2bf_split(v, hi, lo);
            size_t o = ((size_t)b * NN + (size_t)w * WW + r) * DD + n0 + t;
            g_ao_hi[o] = hi; g_ao_lo[o] = lo;
        }
    } else {
        const float bv = bias[n0 + t];
        #pragma unroll 4
        for (int r = 0; r < 128; r++)
            dOut[(size_t)(m0 + r) * DD + n0 + t] = stg[r * 257 + t] + bv;
    }
}

// ---------------------------------------------------------------------------
// Converters — destinations are device globals referenced IN DEVICE CODE ONLY
// ---------------------------------------------------------------------------
__global__ void convert_x_kernel(const float* __restrict__ x)
{
    size_t i = ((size_t)blockIdx.x * blockDim.x + threadIdx.x) * 4;
    float4 v = *(const float4*)(x + i);
    float vals[4] = { v.x, v.y, v.z, v.w };
    #pragma unroll
    for (int j = 0; j < 4; j++) {
        __nv_bfloat16 hi, lo; f2bf_split(vals[j], hi, lo);
        g_x_hi[i + j] = hi;
        g_x_lo[i + j] = lo;
    }
}

// dst[n][k] = src[k][n], bf16 hi/lo split; which: 0 -> wqk, 1 -> wo.
__global__ void transpose_convert_w(const float* __restrict__ src, int ld, int which)
{
    __nv_bfloat16* dh = (which == 0) ? g_wqk_hi : g_wo_hi;
    __nv_bfloat16* dl = (which == 0) ? g_wqk_lo : g_wo_lo;
    __shared__ float sh[32][33];
    const int n0 = blockIdx.x * 32, k0 = blockIdx.y * 32;
    const int tx = threadIdx.x, ty = threadIdx.y;
    #pragma unroll
    for (int i = 0; i < 4; i++)
        sh[ty + 8 * i][tx] = src[(size_t)(k0 + ty + 8 * i) * ld + n0 + tx];
    __syncthreads();
    #pragma unroll
    for (int i = 0; i < 4; i++) {
        float v = sh[tx][ty + 8 * i];
        int n = n0 + ty + 8 * i, k = k0 + tx;
        __nv_bfloat16 hi, lo; f2bf_split(v, hi, lo);
        dh[(size_t)n * DD + k] = hi;
        dl[(size_t)n * DD + k] = lo;
    }
}

// kT[b][d][t] = k[b][t][d]. grid: (1024/32, 4096/32, 4), block (32,8)
__global__ void transpose_k_kernel()
{
    __shared__ __nv_bfloat16 shh[32][34];
    __shared__ __nv_bfloat16 shl[32][34];
    const int d0 = blockIdx.x * 32, t0 = blockIdx.y * 32, b = blockIdx.z;
    const int tx = threadIdx.x, ty = threadIdx.y;
    #pragma unroll
    for (int i = 0; i < 4; i++) {
        int tok = t0 + ty + 8 * i;
        size_t o = ((size_t)b * NN + tok) * DD + d0 + tx;
        shh[ty + 8 * i][tx] = g_k_hi[o];
        shl[ty + 8 * i][tx] = g_k_lo[o];
    }
    __syncthreads();
    #pragma unroll
    for (int i = 0; i < 4; i++) {
        int d = d0 + ty + 8 * i;
        size_t o = ((size_t)b * DD + d) * NN + t0 + tx;
        g_kT_hi[o] = shh[tx][ty + 8 * i];
        g_kT_lo[o] = shl[tx][ty + 8 * i];
    }
}

// ---------------------------------------------------------------------------
extern "C" void kernel_launch(void* const* d_in, const int* in_sizes, int n_in,
                              void* d_out, int out_size)
{
    (void)in_sizes; (void)n_in; (void)out_size;
    const float* x     = (const float*)d_in[0];   // [4,4096,1024]
    const float* w_qkv = (const float*)d_in[1];   // [1024,3072]
    const float* w_out = (const float*)d_in[2];   // [1024,1024]
    const float* b_out = (const float*)d_in[3];   // [1024]
    float* out = (float*)d_out;                   // [4,4096,1024]

    cudaFuncSetAttribute(mma_gemm, cudaFuncAttributeMaxDynamicSharedMemorySize, SMEMB);

    // 1) split inputs into bf16 hi/lo
    convert_x_kernel<<<MTOT * DD / 1024, 256>>>(x);
    transpose_convert_w<<<dim3(64, 32), dim3(32, 8)>>>(w_qkv, 3072, 0);
    transpose_convert_w<<<dim3(32, 32), dim3(32, 8)>>>(w_out, 1024, 1);

    // 2) qk = x @ w_qkv[:, :2048]   (mma.sync bf16x3)
    mma_gemm<<<dim3(8, 128), 256, SMEMB>>>(0, nullptr, nullptr);

    // 3) k transposed per batch for the attn*V GEMM
    transpose_k_kernel<<<dim3(32, 128, 4), dim3(32, 8)>>>();

    // 4) sim = q @ k2^T, softmax fused (unnormalized exp + invsum)
    mma_gemm<<<dim3(NWIN, BB), 256, SMEMB>>>(1, nullptr, nullptr);

    // 5) ao = attn @ k2 (values == keys per reference bug)
    mma_gemm<<<dim3(4, NWIN, BB), 256, SMEMB>>>(2, nullptr, nullptr);

    // 6) out = ao @ w_out + b_out
    mma_gemm<<<dim3(4, 128), 256, SMEMB>>>(3, out, b_out);
}

// round 9
// speedup vs baseline: 3.0528x; 1.0912x over previous
#include <cuda_runtime.h>
#include <cuda_bf16.h>
#include <cstdint>
#include <math.h>
#include <float.h>

#define BB   4
#define NN   4096
#define DD   1024
#define WW   128
#define NWIN (NN / WW)          // 32
#define MTOT (BB * NN)          // 16384

// ---------------------------------------------------------------------------
// bf16 hi/lo split scratch. ONLY referenced from device code — NEVER passed
// as kernel args from host (host-side &symbol is the shadow copy; GB300 ATS
// makes writes to it silently land in host memory).
// ---------------------------------------------------------------------------
__device__ __nv_bfloat16 g_x_hi  [(size_t)MTOT * DD];
__device__ __nv_bfloat16 g_x_lo  [(size_t)MTOT * DD];
__device__ __nv_bfloat16 g_wqk_hi[(size_t)2048 * DD];   // [n][k] = w_qkv[k][n]
__device__ __nv_bfloat16 g_wqk_lo[(size_t)2048 * DD];
__device__ __nv_bfloat16 g_wo_hi [(size_t)1024 * DD];   // [n][k] = w_out[k][n]
__device__ __nv_bfloat16 g_wo_lo [(size_t)1024 * DD];
__device__ __nv_bfloat16 g_q_hi  [(size_t)MTOT * DD];
__device__ __nv_bfloat16 g_q_lo  [(size_t)MTOT * DD];
__device__ __nv_bfloat16 g_k_hi  [(size_t)MTOT * DD];
__device__ __nv_bfloat16 g_k_lo  [(size_t)MTOT * DD];
__device__ __nv_bfloat16 g_kT_hi [(size_t)BB * DD * NN]; // [b][d][t]
__device__ __nv_bfloat16 g_kT_lo [(size_t)BB * DD * NN];
__device__ __nv_bfloat16 g_attn_hi[(size_t)MTOT * 256];  // unnormalized exp
__device__ __nv_bfloat16 g_attn_lo[(size_t)MTOT * 256];
__device__ __nv_bfloat16 g_ao_hi [(size_t)MTOT * DD];
__device__ __nv_bfloat16 g_ao_lo [(size_t)MTOT * DD];
__device__ float         g_invsum[MTOT];

// ---------------------------------------------------------------------------
// primitives
// ---------------------------------------------------------------------------
__device__ __forceinline__ uint32_t smem_u32(const void* p) {
    uint32_t a;
    asm("{ .reg .u64 t; cvta.to.shared.u64 t, %1; cvt.u32.u64 %0, t; }"
        : "=r"(a) : "l"(p));
    return a;
}

__device__ __forceinline__ void mma16816(float* c, const uint32_t* a, const uint32_t* b) {
    asm volatile(
        "mma.sync.aligned.m16n8k16.row.col.f32.bf16.bf16.f32 "
        "{%0,%1,%2,%3}, {%4,%5,%6,%7}, {%8,%9}, {%0,%1,%2,%3};"
        : "+f"(c[0]), "+f"(c[1]), "+f"(c[2]), "+f"(c[3])
        : "r"(a[0]), "r"(a[1]), "r"(a[2]), "r"(a[3]), "r"(b[0]), "r"(b[1]));
}

__device__ __forceinline__ void ldsm_x4(uint32_t& d0, uint32_t& d1,
                                        uint32_t& d2, uint32_t& d3, uint32_t a) {
    asm volatile("ldmatrix.sync.aligned.m8n8.x4.shared.b16 {%0,%1,%2,%3}, [%4];"
                 : "=r"(d0), "=r"(d1), "=r"(d2), "=r"(d3) : "r"(a));
}

__device__ __forceinline__ void cp16(uint32_t dst, const void* src) {
    asm volatile("cp.async.cg.shared.global [%0], [%1], 16;"
                 :: "r"(dst), "l"(src) : "memory");
}
#define CP_COMMIT() asm volatile("cp.async.commit_group;" ::: "memory")
#define CP_WAIT1()  asm volatile("cp.async.wait_group 1;" ::: "memory")

__device__ __forceinline__ void f2bf_split(float v, __nv_bfloat16& hi, __nv_bfloat16& lo) {
    hi = __float2bfloat16(v);
    lo = __float2bfloat16(v - __bfloat162float(hi));
}

// smem per buffer: K-chunk 32 -> 64B data + 16B pad = 80B row stride.
//   A_hi [128][80] @ 0      (10240 B)   A_lo @ 10240
//   B_hi [256][80] @ 20480  (20480 B)   B_lo @ 40960
#define RS    80
#define A_HI  0
#define A_LO  10240
#define B_HI  20480
#define B_LO  40960
#define BUFB  61440
#define NBUF  3
#define SMEMB (NBUF * BUFB)     // 184320; stg 128*257*4=131584 aliases it

// ---------------------------------------------------------------------------
// async chunk loader (A[128]x32 + B[256]x32, hi+lo), masked blocks zero-stored
// ---------------------------------------------------------------------------
__device__ __forceinline__ void load_chunk_async(
    char* sm, uint32_t smb, int cc, int bufIdx, int stage, int w, int t,
    const __nv_bfloat16* Ah, const __nv_bfloat16* Al,
    const __nv_bfloat16* Bh, const __nv_bfloat16* Bl,
    long long aBase, long long bBase, int Astr, int Bstr)
{
    const int kE = cc * 32;
    const uint32_t bo = (uint32_t)bufIdx * BUFB;
    const uint4 z = make_uint4(0u, 0u, 0u, 0u);
    // A: 128 rows x 4 segs of 16B -> 2 segs/thread (hi + lo each)
    #pragma unroll
    for (int i = 0; i < 2; i++) {
        const int idx = t + i * 256;
        const int r = idx >> 2, sg = idx & 3;
        const long long off = aBase + (long long)r * Astr + kE + sg * 8;
        const uint32_t d = smb + bo + A_HI + r * RS + sg * 16;
        cp16(d, Ah + off);
        cp16(d + (A_LO - A_HI), Al + off);
    }
    // B: 256 rows x 4 segs of 16B -> 4 segs/thread (hi + lo each)
    #pragma unroll
    for (int i = 0; i < 4; i++) {
        const int idx = t + i * 256;
        const int r = idx >> 2, sg = idx & 3;
        bool v = true;
        if (stage == 1) v = (w > 0) || (r >= 128);
        if (stage == 2) v = (w > 0) || (cc >= 4);
        const int o = B_HI + r * RS + sg * 16;
        if (v) {
            const long long off = bBase + (long long)r * Bstr + kE + sg * 8;
            cp16(smb + bo + o, Bh + off);
            cp16(smb + bo + o + (B_LO - B_HI), Bl + off);
        } else {
            *(uint4*)(sm + bo + o) = z;
            *(uint4*)(sm + bo + o + (B_LO - B_HI)) = z;
        }
    }
}

// ---------------------------------------------------------------------------
// one K-chunk (k=32, two k16 steps): bf16x3 (AhBh + AhBl + AlBh) via ldmatrix
// ---------------------------------------------------------------------------
__device__ __forceinline__ void compute_chunk(
    uint32_t bufAdd, const uint32_t* aAddr, const uint32_t* bAddr,
    float (&acc)[4][8][4])
{
    #pragma unroll
    for (int kk = 0; kk < 2; kk++) {
        const uint32_t kb = bufAdd + (uint32_t)kk * 32u;
        uint32_t A[4][4], B0[8][2], B1[8][2];
        #pragma unroll
        for (int fm = 0; fm < 4; fm++)
            ldsm_x4(A[fm][0], A[fm][1], A[fm][2], A[fm][3], aAddr[fm] + kb);
        #pragma unroll
        for (int p = 0; p < 4; p++)
            ldsm_x4(B0[2*p][0], B0[2*p][1], B0[2*p+1][0], B0[2*p+1][1],
                    bAddr[p] + kb);
        #pragma unroll
        for (int fm = 0; fm < 4; fm++)
            #pragma unroll
            for (int fn = 0; fn < 8; fn++)
                mma16816(acc[fm][fn], A[fm], B0[fn]);    // Ah*Bh
        #pragma unroll
        for (int p = 0; p < 4; p++)
            ldsm_x4(B1[2*p][0], B1[2*p][1], B1[2*p+1][0], B1[2*p+1][1],
                    bAddr[p] + kb + (B_LO - B_HI));
        #pragma unroll
        for (int fm = 0; fm < 4; fm++)
            #pragma unroll
            for (int fn = 0; fn < 8; fn++)
                mma16816(acc[fm][fn], A[fm], B1[fn]);    // Ah*Bl
        #pragma unroll
        for (int fm = 0; fm < 4; fm++)
            ldsm_x4(A[fm][0], A[fm][1], A[fm][2], A[fm][3],
                    aAddr[fm] + kb + (A_LO - A_HI));
        #pragma unroll
        for (int fm = 0; fm < 4; fm++)
            #pragma unroll
            for (int fn = 0; fn < 8; fn++)
                mma16816(acc[fm][fn], A[fm], B0[fn]);    // Al*Bh
    }
}

// ---------------------------------------------------------------------------
// Unified GEMM: D[128,256] = A[128,K] @ B[256,K]^T via mma.sync bf16x3.
// stage 0: QKV   A=x        B=wqkT        K=1024  epi: split into g_q / g_k
// stage 1: QK^T  A=q(win)   B=k(win-1,w)  K=1024  epi: softmax -> attn+invsum
// stage 2: A*V   A=attn     B=kT          K=256   epi: *invsum -> g_ao
// stage 3: OUT   A=ao       B=woT         K=1024  epi: +bias -> d_out (fp32)
// ---------------------------------------------------------------------------
__global__ void __launch_bounds__(256, 1) mma_gemm(int stage,
                                                   float* __restrict__ dOut,
                                                   const float* __restrict__ bias)
{
    extern __shared__ char sm[];
    const uint32_t smb = smem_u32(sm);
    const int t = threadIdx.x;
    const int lane = t & 31, wid = t >> 5;
    const int wm = wid >> 2, wn = wid & 3;
    const int g = lane >> 2, tg = lane & 3;

    int m0 = 0, n0 = 0, b = 0, w = 0;
    if (stage == 0)      { n0 = blockIdx.x * 256; m0 = blockIdx.y * 128; }
    else if (stage == 1) { w = blockIdx.x; b = blockIdx.y; }
    else if (stage == 2) { n0 = blockIdx.x * 256; w = blockIdx.y; b = blockIdx.z; }
    else                 { n0 = blockIdx.x * 256; m0 = blockIdx.y * 128; }

    const int NCH = (stage == 2) ? 8 : 32;

    const __nv_bfloat16 *Ah, *Al, *Bh, *Bl;
    long long aBase, bBase;
    int Astr, Bstr;
    if (stage == 0) {
        Ah = g_x_hi;  Al = g_x_lo;  Bh = g_wqk_hi; Bl = g_wqk_lo;
        aBase = (long long)m0 * DD; bBase = (long long)n0 * DD; Astr = DD; Bstr = DD;
    } else if (stage == 1) {
        Ah = g_q_hi;  Al = g_q_lo;  Bh = g_k_hi;   Bl = g_k_lo;
        aBase = ((long long)b * NN + (long long)w * WW) * DD;
        bBase = ((long long)b * NN + (long long)(w - 1) * WW) * DD;
        Astr = DD; Bstr = DD;
    } else if (stage == 2) {
        Ah = g_attn_hi; Al = g_attn_lo; Bh = g_kT_hi; Bl = g_kT_lo;
        aBase = ((long long)(b * NWIN + w) * WW) * 256;
        bBase = ((long long)(b * DD + n0)) * NN + (long long)(w - 1) * WW;
        Astr = 256; Bstr = NN;
    } else {
        Ah = g_ao_hi; Al = g_ao_lo; Bh = g_wo_hi; Bl = g_wo_lo;
        aBase = (long long)m0 * DD; bBase = (long long)n0 * DD; Astr = DD; Bstr = DD;
    }

    // ldmatrix lane addresses (buffer 0, k16 step 0; add per-chunk offsets)
    uint32_t aAddr[4], bAddr[4];
    {
        const int rowA = lane & 15;
        const int khA  = (lane >> 4) * 16;
        #pragma unroll
        for (int fm = 0; fm < 4; fm++)
            aAddr[fm] = smb + A_HI + (uint32_t)((wm * 64 + fm * 16 + rowA) * RS + khA);
        const int rowB = (lane & 7) + ((lane >> 4) & 1) * 8;
        const int khB  = ((lane >> 3) & 1) * 16;
        #pragma unroll
        for (int p = 0; p < 4; p++)
            bAddr[p] = smb + B_HI + (uint32_t)((wn * 64 + p * 16 + rowB) * RS + khB);
    }

    float acc[4][8][4];
    #pragma unroll
    for (int i = 0; i < 4; i++)
        #pragma unroll
        for (int j = 0; j < 8; j++)
            #pragma unroll
            for (int e = 0; e < 4; e++) acc[i][j][e] = 0.f;

    // prologue: 2 chunks in flight (3 buffers)
    load_chunk_async(sm, smb, 0, 0, stage, w, t, Ah, Al, Bh, Bl, aBase, bBase, Astr, Bstr);
    CP_COMMIT();
    load_chunk_async(sm, smb, 1, 1, stage, w, t, Ah, Al, Bh, Bl, aBase, bBase, Astr, Bstr);
    CP_COMMIT();

    #pragma unroll 1
    for (int c = 0; c < NCH; c++) {
        CP_WAIT1();                    // chunk c's group retired (1 newer allowed)
        __syncthreads();               // all threads' cp.async for chunk c visible
        compute_chunk((uint32_t)((c % 3) * BUFB), aAddr, bAddr, acc);
        const int cc = c + 2;
        if (cc < NCH)
            load_chunk_async(sm, smb, cc, cc % 3, stage, w, t,
                             Ah, Al, Bh, Bl, aBase, bBase, Astr, Bstr);
        CP_COMMIT();                   // empty group when cc >= NCH keeps FIFO exact
    }
    __syncthreads();

    // ---- stage D[128,256] into smem [128][257] fp32 (aliases buffers) ----
    float* stg = (float*)sm;
    #pragma unroll
    for (int fm = 0; fm < 4; fm++) {
        const int r0 = wm * 64 + fm * 16 + g;
        #pragma unroll
        for (int fn = 0; fn < 8; fn++) {
            const int c0 = wn * 64 + fn * 8 + tg * 2;
            stg[r0 * 257 + c0]           = acc[fm][fn][0];
            stg[r0 * 257 + c0 + 1]       = acc[fm][fn][1];
            stg[(r0 + 8) * 257 + c0]     = acc[fm][fn][2];
            stg[(r0 + 8) * 257 + c0 + 1] = acc[fm][fn][3];
        }
    }
    __syncthreads();

    // ---- stage-specific epilogue ----
    const int wg = wid;
    if (stage == 0) {
        const bool isQ = (n0 < 1024);
        __nv_bfloat16* dh = isQ ? g_q_hi : g_k_hi;
        __nv_bfloat16* dl = isQ ? g_q_lo : g_k_lo;
        const int nq = isQ ? n0 : (n0 - 1024);
        #pragma unroll 4
        for (int r = 0; r < 128; r++) {
            float v = stg[r * 257 + t];
            __nv_bfloat16 hi, lo; f2bf_split(v, hi, lo);
            size_t o = (size_t)(m0 + r) * DD + nq + t;
            dh[o] = hi; dl[o] = lo;
        }
    } else if (stage == 1) {
        const int rowbase = (b * NWIN + w) * WW;
        for (int rr = 0; rr < 16; rr++) {
            const int r = wg * 16 + rr;
            float vv[8];
            float mx = -FLT_MAX;
            #pragma unroll
            for (int u = 0; u < 8; u++) {
                int j = lane + u * 32;
                float sc = stg[r * 257 + j] * 0.03125f;
                vv[u] = (j <= r + 128) ? sc : -FLT_MAX;
                mx = fmaxf(mx, vv[u]);
            }
            #pragma unroll
            for (int off = 16; off; off >>= 1)
                mx = fmaxf(mx, __shfl_xor_sync(0xffffffffu, mx, off));
            float sum = 0.f;
            #pragma unroll
            for (int u = 0; u < 8; u++) {
                int j = lane + u * 32;
                float e = (j <= r + 128) ? expf(vv[u] - mx) : 0.f;
                sum += e;
                __nv_bfloat16 hi, lo; f2bf_split(e, hi, lo);
                size_t o = (size_t)(rowbase + r) * 256 + j;
                g_attn_hi[o] = hi; g_attn_lo[o] = lo;
            }
            #pragma unroll
            for (int off = 16; off; off >>= 1)
                sum += __shfl_xor_sync(0xffffffffu, sum, off);
            if (lane == 0) g_invsum[rowbase + r] = 1.f / sum;
        }
    } else if (stage == 2) {
        const int rowbase = (b * NWIN + w) * WW;
        #pragma unroll 4
        for (int r = 0; r < 128; r++) {
            float v = stg[r * 257 + t] * g_invsum[rowbase + r];
            __nv_bfloat16 hi, lo; f2bf_split(v, hi, lo);
            size_t o = ((size_t)b * NN + (size_t)w * WW + r) * DD + n0 + t;
            g_ao_hi[o] = hi; g_ao_lo[o] = lo;
        }
    } else {
        const float bv = bias[n0 + t];
        #pragma unroll 4
        for (int r = 0; r < 128; r++)
            dOut[(size_t)(m0 + r) * DD + n0 + t] = stg[r * 257 + t] + bv;
    }
}

// ---------------------------------------------------------------------------
// Converters — destinations are device globals referenced IN DEVICE CODE ONLY
// ---------------------------------------------------------------------------
__global__ void convert_x_kernel(const float* __restrict__ x)
{
    size_t i = ((size_t)blockIdx.x * blockDim.x + threadIdx.x) * 4;
    float4 v = *(const float4*)(x + i);
    float vals[4] = { v.x, v.y, v.z, v.w };
    #pragma unroll
    for (int j = 0; j < 4; j++) {
        __nv_bfloat16 hi, lo; f2bf_split(vals[j], hi, lo);
        g_x_hi[i + j] = hi;
        g_x_lo[i + j] = lo;
    }
}

// dst[n][k] = src[k][n], bf16 hi/lo split; which: 0 -> wqk, 1 -> wo.
__global__ void transpose_convert_w(const float* __restrict__ src, int ld, int which)
{
    __nv_bfloat16* dh = (which == 0) ? g_wqk_hi : g_wo_hi;
    __nv_bfloat16* dl = (which == 0) ? g_wqk_lo : g_wo_lo;
    __shared__ float sh[32][33];
    const int n0 = blockIdx.x * 32, k0 = blockIdx.y * 32;
    const int tx = threadIdx.x, ty = threadIdx.y;
    #pragma unroll
    for (int i = 0; i < 4; i++)
        sh[ty + 8 * i][tx] = src[(size_t)(k0 + ty + 8 * i) * ld + n0 + tx];
    __syncthreads();
    #pragma unroll
    for (int i = 0; i < 4; i++) {
        float v = sh[tx][ty + 8 * i];
        int n = n0 + ty + 8 * i, k = k0 + tx;
        __nv_bfloat16 hi, lo; f2bf_split(v, hi, lo);
        dh[(size_t)n * DD + k] = hi;
        dl[(size_t)n * DD + k] = lo;
    }
}

// kT[b][d][t] = k[b][t][d]. grid: (1024/32, 4096/32, 4), block (32,8)
__global__ void transpose_k_kernel()
{
    __shared__ __nv_bfloat16 shh[32][34];
    __shared__ __nv_bfloat16 shl[32][34];
    const int d0 = blockIdx.x * 32, t0 = blockIdx.y * 32, b = blockIdx.z;
    const int tx = threadIdx.x, ty = threadIdx.y;
    #pragma unroll
    for (int i = 0; i < 4; i++) {
        int tok = t0 + ty + 8 * i;
        size_t o = ((size_t)b * NN + tok) * DD + d0 + tx;
        shh[ty + 8 * i][tx] = g_k_hi[o];
        shl[ty + 8 * i][tx] = g_k_lo[o];
    }
    __syncthreads();
    #pragma unroll
    for (int i = 0; i < 4; i++) {
        int d = d0 + ty + 8 * i;
        size_t o = ((size_t)b * DD + d) * NN + t0 + tx;
        g_kT_hi[o] = shh[tx][ty + 8 * i];
        g_kT_lo[o] = shl[tx][ty + 8 * i];
    }
}

// ---------------------------------------------------------------------------
extern "C" void kernel_launch(void* const* d_in, const int* in_sizes, int n_in,
                              void* d_out, int out_size)
{
    (void)in_sizes; (void)n_in; (void)out_size;
    const float* x     = (const float*)d_in[0];   // [4,4096,1024]
    const float* w_qkv = (const float*)d_in[1];   // [1024,3072]
    const float* w_out = (const float*)d_in[2];   // [1024,1024]
    const float* b_out = (const float*)d_in[3];   // [1024]
    float* out = (float*)d_out;                   // [4,4096,1024]

    cudaFuncSetAttribute(mma_gemm, cudaFuncAttributeMaxDynamicSharedMemorySize, SMEMB);

    // 1) split inputs into bf16 hi/lo
    convert_x_kernel<<<MTOT * DD / 1024, 256>>>(x);
    transpose_convert_w<<<dim3(64, 32), dim3(32, 8)>>>(w_qkv, 3072, 0);
    transpose_convert_w<<<dim3(32, 32), dim3(32, 8)>>>(w_out, 1024, 1);

    // 2) qk = x @ w_qkv[:, :2048]   (mma.sync bf16x3)
    mma_gemm<<<dim3(8, 128), 256, SMEMB>>>(0, nullptr, nullptr);

    // 3) k transposed per batch for the attn*V GEMM
    transpose_k_kernel<<<dim3(32, 128, 4), dim3(32, 8)>>>();

    // 4) sim = q @ k2^T, softmax fused (unnormalized exp + invsum)
    mma_gemm<<<dim3(NWIN, BB), 256, SMEMB>>>(1, nullptr, nullptr);

    // 5) ao = attn @ k2 (values == keys per reference bug)
    mma_gemm<<<dim3(4, NWIN, BB), 256, SMEMB>>>(2, nullptr, nullptr);

    // 6) out = ao @ w_out + b_out
    mma_gemm<<<dim3(4, 128), 256, SMEMB>>>(3, out, b_out);
}

// round 10
// speedup vs baseline: 3.2124x; 1.0523x over previous
#include <cuda_runtime.h>
#include <cuda_bf16.h>
#include <cstdint>
#include <math.h>
#include <float.h>

#define BB   4
#define NN   4096
#define DD   1024
#define WW   128
#define NWIN (NN / WW)          // 32
#define MTOT (BB * NN)          // 16384

// ---------------------------------------------------------------------------
// bf16 hi/lo split scratch. ONLY referenced from device code — NEVER passed
// as kernel args from host (host-side &symbol is the shadow copy; GB300 ATS
// makes writes to it silently land in host memory).
// ---------------------------------------------------------------------------
__device__ __nv_bfloat16 g_x_hi  [(size_t)MTOT * DD];
__device__ __nv_bfloat16 g_x_lo  [(size_t)MTOT * DD];
__device__ __nv_bfloat16 g_wqk_hi[(size_t)2048 * DD];   // [n][k] = w_qkv[k][n]
__device__ __nv_bfloat16 g_wqk_lo[(size_t)2048 * DD];
__device__ __nv_bfloat16 g_wo_hi [(size_t)1024 * DD];   // [n][k] = w_out[k][n]
__device__ __nv_bfloat16 g_wo_lo [(size_t)1024 * DD];
__device__ __nv_bfloat16 g_q_hi  [(size_t)MTOT * DD];
__device__ __nv_bfloat16 g_q_lo  [(size_t)MTOT * DD];
__device__ __nv_bfloat16 g_k_hi  [(size_t)MTOT * DD];
__device__ __nv_bfloat16 g_k_lo  [(size_t)MTOT * DD];
__device__ __nv_bfloat16 g_kT_hi [(size_t)BB * DD * NN]; // [b][d][t]
__device__ __nv_bfloat16 g_kT_lo [(size_t)BB * DD * NN];
__device__ __nv_bfloat16 g_attn_hi[(size_t)MTOT * 256];  // unnormalized exp
__device__ __nv_bfloat16 g_attn_lo[(size_t)MTOT * 256];
__device__ __nv_bfloat16 g_ao_hi [(size_t)MTOT * DD];
__device__ __nv_bfloat16 g_ao_lo [(size_t)MTOT * DD];
__device__ float         g_invsum[MTOT];

// ---------------------------------------------------------------------------
// primitives
// ---------------------------------------------------------------------------
__device__ __forceinline__ uint32_t smem_u32(const void* p) {
    uint32_t a;
    asm("{ .reg .u64 t; cvta.to.shared.u64 t, %1; cvt.u32.u64 %0, t; }"
        : "=r"(a) : "l"(p));
    return a;
}

__device__ __forceinline__ void mma16816(float* c, const uint32_t* a, const uint32_t* b) {
    asm volatile(
        "mma.sync.aligned.m16n8k16.row.col.f32.bf16.bf16.f32 "
        "{%0,%1,%2,%3}, {%4,%5,%6,%7}, {%8,%9}, {%0,%1,%2,%3};"
        : "+f"(c[0]), "+f"(c[1]), "+f"(c[2]), "+f"(c[3])
        : "r"(a[0]), "r"(a[1]), "r"(a[2]), "r"(a[3]), "r"(b[0]), "r"(b[1]));
}

__device__ __forceinline__ void ldsm_x4(uint32_t& d0, uint32_t& d1,
                                        uint32_t& d2, uint32_t& d3, uint32_t a) {
    asm volatile("ldmatrix.sync.aligned.m8n8.x4.shared.b16 {%0,%1,%2,%3}, [%4];"
                 : "=r"(d0), "=r"(d1), "=r"(d2), "=r"(d3) : "r"(a));
}

__device__ __forceinline__ void cp16(uint32_t dst, const void* src) {
    asm volatile("cp.async.cg.shared.global [%0], [%1], 16;"
                 :: "r"(dst), "l"(src) : "memory");
}
#define CP_COMMIT() asm volatile("cp.async.commit_group;" ::: "memory")
#define CP_WAIT1()  asm volatile("cp.async.wait_group 1;" ::: "memory")

__device__ __forceinline__ void f2bf_split(float v, __nv_bfloat16& hi, __nv_bfloat16& lo) {
    hi = __float2bfloat16(v);
    lo = __float2bfloat16(v - __bfloat162float(hi));
}

// smem per buffer: K-chunk 32 -> 64B data + 16B pad = 80B row stride.
//   A_hi [128][80] @ 0      (10240 B)   A_lo @ 10240
//   B_hi [256][80] @ 20480  (20480 B)   B_lo @ 40960
#define RS    80
#define A_HI  0
#define A_LO  10240
#define B_HI  20480
#define B_LO  40960
#define BUFB  61440
#define NBUF  3
#define SMEMB (NBUF * BUFB)     // 184320; stg 128*257*4=131584 aliases it

#define NT    512               // 16 warps: 4x4 warp grid, warp tile 32x64

// ---------------------------------------------------------------------------
// async chunk loader (A[128]x32 + B[256]x32, hi+lo), masked blocks zero-stored
// 512 threads: A = 1 seg/thread, B = 2 segs/thread (hi+lo each)
// ---------------------------------------------------------------------------
__device__ __forceinline__ void load_chunk_async(
    char* sm, uint32_t smb, int cc, int bufIdx, int stage, int w, int t,
    const __nv_bfloat16* Ah, const __nv_bfloat16* Al,
    const __nv_bfloat16* Bh, const __nv_bfloat16* Bl,
    long long aBase, long long bBase, int Astr, int Bstr)
{
    const int kE = cc * 32;
    const uint32_t bo = (uint32_t)bufIdx * BUFB;
    const uint4 z = make_uint4(0u, 0u, 0u, 0u);
    // A: 128 rows x 4 segs of 16B = 512 segs
    {
        const int r = t >> 2, sg = t & 3;
        const long long off = aBase + (long long)r * Astr + kE + sg * 8;
        const uint32_t d = smb + bo + A_HI + r * RS + sg * 16;
        cp16(d, Ah + off);
        cp16(d + (A_LO - A_HI), Al + off);
    }
    // B: 256 rows x 4 segs of 16B = 1024 segs
    #pragma unroll
    for (int i = 0; i < 2; i++) {
        const int idx = t + i * NT;
        const int r = idx >> 2, sg = idx & 3;
        bool v = true;
        if (stage == 1) v = (w > 0) || (r >= 128);
        if (stage == 2) v = (w > 0) || (cc >= 4);
        const int o = B_HI + r * RS + sg * 16;
        if (v) {
            const long long off = bBase + (long long)r * Bstr + kE + sg * 8;
            cp16(smb + bo + o, Bh + off);
            cp16(smb + bo + o + (B_LO - B_HI), Bl + off);
        } else {
            *(uint4*)(sm + bo + o) = z;
            *(uint4*)(sm + bo + o + (B_LO - B_HI)) = z;
        }
    }
}

// ---------------------------------------------------------------------------
// one K-chunk (k=32, two k16 steps): bf16x3 (AhBh + AhBl + AlBh) via ldmatrix
// warp tile 32x64: A frags 2, B frags 8
// ---------------------------------------------------------------------------
__device__ __forceinline__ void compute_chunk(
    uint32_t bufAdd, const uint32_t* aAddr, const uint32_t* bAddr,
    float (&acc)[2][8][4])
{
    #pragma unroll
    for (int kk = 0; kk < 2; kk++) {
        const uint32_t kb = bufAdd + (uint32_t)kk * 32u;
        uint32_t A[2][4], B0[8][2], B1[8][2];
        #pragma unroll
        for (int fm = 0; fm < 2; fm++)
            ldsm_x4(A[fm][0], A[fm][1], A[fm][2], A[fm][3], aAddr[fm] + kb);
        #pragma unroll
        for (int p = 0; p < 4; p++)
            ldsm_x4(B0[2*p][0], B0[2*p][1], B0[2*p+1][0], B0[2*p+1][1],
                    bAddr[p] + kb);
        #pragma unroll
        for (int fm = 0; fm < 2; fm++)
            #pragma unroll
            for (int fn = 0; fn < 8; fn++)
                mma16816(acc[fm][fn], A[fm], B0[fn]);    // Ah*Bh
        #pragma unroll
        for (int p = 0; p < 4; p++)
            ldsm_x4(B1[2*p][0], B1[2*p][1], B1[2*p+1][0], B1[2*p+1][1],
                    bAddr[p] + kb + (B_LO - B_HI));
        #pragma unroll
        for (int fm = 0; fm < 2; fm++)
            #pragma unroll
            for (int fn = 0; fn < 8; fn++)
                mma16816(acc[fm][fn], A[fm], B1[fn]);    // Ah*Bl
        #pragma unroll
        for (int fm = 0; fm < 2; fm++)
            ldsm_x4(A[fm][0], A[fm][1], A[fm][2], A[fm][3],
                    aAddr[fm] + kb + (A_LO - A_HI));
        #pragma unroll
        for (int fm = 0; fm < 2; fm++)
            #pragma unroll
            for (int fn = 0; fn < 8; fn++)
                mma16816(acc[fm][fn], A[fm], B0[fn]);    // Al*Bh
    }
}

// ---------------------------------------------------------------------------
// Unified GEMM: D[128,256] = A[128,K] @ B[256,K]^T via mma.sync bf16x3.
// stage 0: QKV   A=x        B=wqkT        K=1024  epi: split into g_q / g_k
// stage 1: QK^T  A=q(win)   B=k(win-1,w)  K=1024  epi: softmax -> attn+invsum
// stage 2: A*V   A=attn     B=kT          K=256   epi: *invsum -> g_ao
// stage 3: OUT   A=ao       B=woT         K=1024  epi: +bias -> d_out (fp32)
// ---------------------------------------------------------------------------
__global__ void __launch_bounds__(NT, 1) mma_gemm(int stage,
                                                  float* __restrict__ dOut,
                                                  const float* __restrict__ bias)
{
    extern __shared__ char sm[];
    const uint32_t smb = smem_u32(sm);
    const int t = threadIdx.x;
    const int lane = t & 31, wid = t >> 5;
    const int wm = wid & 3, wn = wid >> 2;     // 4 M-slices x 4 N-slices
    const int g = lane >> 2, tg = lane & 3;

    int m0 = 0, n0 = 0, b = 0, w = 0;
    if (stage == 0)      { n0 = blockIdx.x * 256; m0 = blockIdx.y * 128; }
    else if (stage == 1) { w = blockIdx.x; b = blockIdx.y; }
    else if (stage == 2) { n0 = blockIdx.x * 256; w = blockIdx.y; b = blockIdx.z; }
    else                 { n0 = blockIdx.x * 256; m0 = blockIdx.y * 128; }

    const int NCH = (stage == 2) ? 8 : 32;

    const __nv_bfloat16 *Ah, *Al, *Bh, *Bl;
    long long aBase, bBase;
    int Astr, Bstr;
    if (stage == 0) {
        Ah = g_x_hi;  Al = g_x_lo;  Bh = g_wqk_hi; Bl = g_wqk_lo;
        aBase = (long long)m0 * DD; bBase = (long long)n0 * DD; Astr = DD; Bstr = DD;
    } else if (stage == 1) {
        Ah = g_q_hi;  Al = g_q_lo;  Bh = g_k_hi;   Bl = g_k_lo;
        aBase = ((long long)b * NN + (long long)w * WW) * DD;
        bBase = ((long long)b * NN + (long long)(w - 1) * WW) * DD;
        Astr = DD; Bstr = DD;
    } else if (stage == 2) {
        Ah = g_attn_hi; Al = g_attn_lo; Bh = g_kT_hi; Bl = g_kT_lo;
        aBase = ((long long)(b * NWIN + w) * WW) * 256;
        bBase = ((long long)(b * DD + n0)) * NN + (long long)(w - 1) * WW;
        Astr = 256; Bstr = NN;
    } else {
        Ah = g_ao_hi; Al = g_ao_lo; Bh = g_wo_hi; Bl = g_wo_lo;
        aBase = (long long)m0 * DD; bBase = (long long)n0 * DD; Astr = DD; Bstr = DD;
    }

    // ldmatrix lane addresses (buffer 0, k16 step 0; add per-chunk offsets)
    uint32_t aAddr[2], bAddr[4];
    {
        const int rowA = lane & 15;
        const int khA  = (lane >> 4) * 16;
        #pragma unroll
        for (int fm = 0; fm < 2; fm++)
            aAddr[fm] = smb + A_HI + (uint32_t)((wm * 32 + fm * 16 + rowA) * RS + khA);
        const int rowB = (lane & 7) + ((lane >> 4) & 1) * 8;
        const int khB  = ((lane >> 3) & 1) * 16;
        #pragma unroll
        for (int p = 0; p < 4; p++)
            bAddr[p] = smb + B_HI + (uint32_t)((wn * 64 + p * 16 + rowB) * RS + khB);
    }

    float acc[2][8][4];
    #pragma unroll
    for (int i = 0; i < 2; i++)
        #pragma unroll
        for (int j = 0; j < 8; j++)
            #pragma unroll
            for (int e = 0; e < 4; e++) acc[i][j][e] = 0.f;

    // prologue: 2 chunks in flight (3 buffers)
    load_chunk_async(sm, smb, 0, 0, stage, w, t, Ah, Al, Bh, Bl, aBase, bBase, Astr, Bstr);
    CP_COMMIT();
    load_chunk_async(sm, smb, 1, 1, stage, w, t, Ah, Al, Bh, Bl, aBase, bBase, Astr, Bstr);
    CP_COMMIT();

    #pragma unroll 1
    for (int c = 0; c < NCH; c++) {
        CP_WAIT1();                    // chunk c's group retired (1 newer allowed)
        __syncthreads();               // all threads' cp.async for chunk c visible
        compute_chunk((uint32_t)((c % 3) * BUFB), aAddr, bAddr, acc);
        const int cc = c + 2;
        if (cc < NCH)
            load_chunk_async(sm, smb, cc, cc % 3, stage, w, t,
                             Ah, Al, Bh, Bl, aBase, bBase, Astr, Bstr);
        CP_COMMIT();                   // empty group when cc >= NCH keeps FIFO exact
    }
    __syncthreads();

    // ---- stage D[128,256] into smem [128][257] fp32 (aliases buffers) ----
    float* stg = (float*)sm;
    #pragma unroll
    for (int fm = 0; fm < 2; fm++) {
        const int r0 = wm * 32 + fm * 16 + g;
        #pragma unroll
        for (int fn = 0; fn < 8; fn++) {
            const int c0 = wn * 64 + fn * 8 + tg * 2;
            stg[r0 * 257 + c0]           = acc[fm][fn][0];
            stg[r0 * 257 + c0 + 1]       = acc[fm][fn][1];
            stg[(r0 + 8) * 257 + c0]     = acc[fm][fn][2];
            stg[(r0 + 8) * 257 + c0 + 1] = acc[fm][fn][3];
        }
    }
    __syncthreads();

    // ---- stage-specific epilogue (512 threads: col = t&255, 2 row-slices) --
    const int wg = wid;
    const int col = t & 255;
    const int rb  = t >> 8;            // 0 or 1
    if (stage == 0) {
        const bool isQ = (n0 < 1024);
        __nv_bfloat16* dh = isQ ? g_q_hi : g_k_hi;
        __nv_bfloat16* dl = isQ ? g_q_lo : g_k_lo;
        const int nq = isQ ? n0 : (n0 - 1024);
        #pragma unroll 4
        for (int rr = 0; rr < 64; rr++) {
            const int r = rb + rr * 2;
            float v = stg[r * 257 + col];
            __nv_bfloat16 hi, lo; f2bf_split(v, hi, lo);
            size_t o = (size_t)(m0 + r) * DD + nq + col;
            dh[o] = hi; dl[o] = lo;
        }
    } else if (stage == 1) {
        const int rowbase = (b * NWIN + w) * WW;
        for (int rr = 0; rr < 8; rr++) {
            const int r = wg * 8 + rr;
            float vv[8];
            float mx = -FLT_MAX;
            #pragma unroll
            for (int u = 0; u < 8; u++) {
                int j = lane + u * 32;
                float sc = stg[r * 257 + j] * 0.03125f;
                vv[u] = (j <= r + 128) ? sc : -FLT_MAX;
                mx = fmaxf(mx, vv[u]);
            }
            #pragma unroll
            for (int off = 16; off; off >>= 1)
                mx = fmaxf(mx, __shfl_xor_sync(0xffffffffu, mx, off));
            float sum = 0.f;
            #pragma unroll
            for (int u = 0; u < 8; u++) {
                int j = lane + u * 32;
                float e = (j <= r + 128) ? expf(vv[u] - mx) : 0.f;
                sum += e;
                __nv_bfloat16 hi, lo; f2bf_split(e, hi, lo);
                size_t o = (size_t)(rowbase + r) * 256 + j;
                g_attn_hi[o] = hi; g_attn_lo[o] = lo;
            }
            #pragma unroll
            for (int off = 16; off; off >>= 1)
                sum += __shfl_xor_sync(0xffffffffu, sum, off);
            if (lane == 0) g_invsum[rowbase + r] = 1.f / sum;
        }
    } else if (stage == 2) {
        const int rowbase = (b * NWIN + w) * WW;
        #pragma unroll 4
        for (int rr = 0; rr < 64; rr++) {
            const int r = rb + rr * 2;
            float v = stg[r * 257 + col] * g_invsum[rowbase + r];
            __nv_bfloat16 hi, lo; f2bf_split(v, hi, lo);
            size_t o = ((size_t)b * NN + (size_t)w * WW + r) * DD + n0 + col;
            g_ao_hi[o] = hi; g_ao_lo[o] = lo;
        }
    } else {
        const float bv = bias[n0 + col];
        #pragma unroll 4
        for (int rr = 0; rr < 64; rr++) {
            const int r = rb + rr * 2;
            dOut[(size_t)(m0 + r) * DD + n0 + col] = stg[r * 257 + col] + bv;
        }
    }
}

// ---------------------------------------------------------------------------
// Converters — destinations are device globals referenced IN DEVICE CODE ONLY
// ---------------------------------------------------------------------------
__global__ void convert_x_kernel(const float* __restrict__ x)
{
    size_t i = ((size_t)blockIdx.x * blockDim.x + threadIdx.x) * 4;
    float4 v = *(const float4*)(x + i);
    float vals[4] = { v.x, v.y, v.z, v.w };
    #pragma unroll
    for (int j = 0; j < 4; j++) {
        __nv_bfloat16 hi, lo; f2bf_split(vals[j], hi, lo);
        g_x_hi[i + j] = hi;
        g_x_lo[i + j] = lo;
    }
}

// dst[n][k] = src[k][n], bf16 hi/lo split; which: 0 -> wqk, 1 -> wo.
__global__ void transpose_convert_w(const float* __restrict__ src, int ld, int which)
{
    __nv_bfloat16* dh = (which == 0) ? g_wqk_hi : g_wo_hi;
    __nv_bfloat16* dl = (which == 0) ? g_wqk_lo : g_wo_lo;
    __shared__ float sh[32][33];
    const int n0 = blockIdx.x * 32, k0 = blockIdx.y * 32;
    const int tx = threadIdx.x, ty = threadIdx.y;
    #pragma unroll
    for (int i = 0; i < 4; i++)
        sh[ty + 8 * i][tx] = src[(size_t)(k0 + ty + 8 * i) * ld + n0 + tx];
    __syncthreads();
    #pragma unroll
    for (int i = 0; i < 4; i++) {
        float v = sh[tx][ty + 8 * i];
        int n = n0 + ty + 8 * i, k = k0 + tx;
        __nv_bfloat16 hi, lo; f2bf_split(v, hi, lo);
        dh[(size_t)n * DD + k] = hi;
        dl[(size_t)n * DD + k] = lo;
    }
}

// kT[b][d][t] = k[b][t][d]. grid: (1024/32, 4096/32, 4), block (32,8)
__global__ void transpose_k_kernel()
{
    __shared__ __nv_bfloat16 shh[32][34];
    __shared__ __nv_bfloat16 shl[32][34];
    const int d0 = blockIdx.x * 32, t0 = blockIdx.y * 32, b = blockIdx.z;
    const int tx = threadIdx.x, ty = threadIdx.y;
    #pragma unroll
    for (int i = 0; i < 4; i++) {
        int tok = t0 + ty + 8 * i;
        size_t o = ((size_t)b * NN + tok) * DD + d0 + tx;
        shh[ty + 8 * i][tx] = g_k_hi[o];
        shl[ty + 8 * i][tx] = g_k_lo[o];
    }
    __syncthreads();
    #pragma unroll
    for (int i = 0; i < 4; i++) {
        int d = d0 + ty + 8 * i;
        size_t o = ((size_t)b * DD + d) * NN + t0 + tx;
        g_kT_hi[o] = shh[tx][ty + 8 * i];
        g_kT_lo[o] = shl[tx][ty + 8 * i];
    }
}

// ---------------------------------------------------------------------------
extern "C" void kernel_launch(void* const* d_in, const int* in_sizes, int n_in,
                              void* d_out, int out_size)
{
    (void)in_sizes; (void)n_in; (void)out_size;
    const float* x     = (const float*)d_in[0];   // [4,4096,1024]
    const float* w_qkv = (const float*)d_in[1];   // [1024,3072]
    const float* w_out = (const float*)d_in[2];   // [1024,1024]
    const float* b_out = (const float*)d_in[3];   // [1024]
    float* out = (float*)d_out;                   // [4,4096,1024]

    cudaFuncSetAttribute(mma_gemm, cudaFuncAttributeMaxDynamicSharedMemorySize, SMEMB);

    // 1) split inputs into bf16 hi/lo
    convert_x_kernel<<<MTOT * DD / 1024, 256>>>(x);
    transpose_convert_w<<<dim3(64, 32), dim3(32, 8)>>>(w_qkv, 3072, 0);
    transpose_convert_w<<<dim3(32, 32), dim3(32, 8)>>>(w_out, 1024, 1);

    // 2) qk = x @ w_qkv[:, :2048]   (mma.sync bf16x3)
    mma_gemm<<<dim3(8, 128), NT, SMEMB>>>(0, nullptr, nullptr);

    // 3) k transposed per batch for the attn*V GEMM
    transpose_k_kernel<<<dim3(32, 128, 4), dim3(32, 8)>>>();

    // 4) sim = q @ k2^T, softmax fused (unnormalized exp + invsum)
    mma_gemm<<<dim3(NWIN, BB), NT, SMEMB>>>(1, nullptr, nullptr);

    // 5) ao = attn @ k2 (values == keys per reference bug)
    mma_gemm<<<dim3(4, NWIN, BB), NT, SMEMB>>>(2, nullptr, nullptr);

    // 6) out = ao @ w_out + b_out
    mma_gemm<<<dim3(4, 128), NT, SMEMB>>>(3, out, b_out);
}